// round 3
// baseline (speedup 1.0000x reference)
#include <cuda_runtime.h>
#include <math.h>

// Problem dims (fixed per reference setup_inputs)
#define L_DIM 2048
#define S_DIM 2048
#define B_DIM 4
#define E_DIM 1024
#define N_ROWS (L_DIM * B_DIM)   // 8192 flattened (l,b) rows
#define M_MAX  2048              // max(L, S)
#define HALF_PI 1.5707963267948966f
#define EPS_F 1e-6f

typedef unsigned long long u64;

// ---------------------------------------------------------------------------
// f32x2 packed helpers (sm_103a FFMA2 path — ptxas never auto-fuses this)
// ---------------------------------------------------------------------------
__device__ __forceinline__ u64 pack2(float x, float y) {
    u64 r; asm("mov.b64 %0,{%1,%2};" : "=l"(r) : "f"(x), "f"(y)); return r;
}
__device__ __forceinline__ void unpack2(u64 v, float& x, float& y) {
    asm("mov.b64 {%0,%1},%2;" : "=f"(x), "=f"(y) : "l"(v));
}
__device__ __forceinline__ u64 ffma2(u64 a, u64 b, u64 c) {
    u64 d; asm("fma.rn.f32x2 %0,%1,%2,%3;" : "=l"(d) : "l"(a), "l"(b), "l"(c)); return d;
}
__device__ __forceinline__ u64 fmul2(u64 a, u64 b) {
    u64 d; asm("mul.rn.f32x2 %0,%1,%2;" : "=l"(d) : "l"(a), "l"(b)); return d;
}

// ---------------------------------------------------------------------------
// Scratch (no allocation allowed -> __device__ globals)
// ---------------------------------------------------------------------------
__device__ float g_Qp[N_ROWS * E_DIM];
__device__ float g_Kp[N_ROWS * E_DIM];
__device__ float g_Vp[N_ROWS * E_DIM];
__device__ float g_KVs[B_DIM * E_DIM * E_DIM];
__device__ float g_KVc[B_DIM * E_DIM * E_DIM];
__device__ float g_Ks[B_DIM * E_DIM];
__device__ float g_Kc[B_DIM * E_DIM];
__device__ float g_KsP[16 * B_DIM * E_DIM];   // colsum partials (16 s-chunks)
__device__ float g_KcP[16 * B_DIM * E_DIM];
__device__ float g_Z[N_ROWS];

// ---------------------------------------------------------------------------
// Stage 1: projection GEMM with FFMA2.
// P[n,f] = act( sum_e X[n,e]*W[f,e] + bias[f] )
// Tile BM=128 (n), BN=64 (f), BK=16. 256 threads; per-thread 8x4 as 4x4 f32x2.
// ---------------------------------------------------------------------------
template <bool RELU>
__global__ __launch_bounds__(256)
void proj_kernel(const float* __restrict__ X, const float* __restrict__ W,
                 const float* __restrict__ bias, float* __restrict__ P) {
    __shared__ __align__(16) float As[16][132];    // [k][m], transposed
    __shared__ __align__(16) float Bsd[16][136];   // [k][2f], b duplicated {b,b}

    const int n0 = blockIdx.y * 128;
    const int f0 = blockIdx.x * 64;
    const int tid = threadIdx.x;
    const int ty = tid >> 4;        // rows ty*8..ty*8+7
    const int tx = tid & 15;        // cols tx*4..tx*4+3

    u64 acc2[4][4];
#pragma unroll
    for (int i = 0; i < 4; i++)
#pragma unroll
        for (int j = 0; j < 4; j++) acc2[i][j] = 0ULL;

    for (int kt = 0; kt < E_DIM; kt += 16) {
        // A tile 128x16 -> transpose into As[k][m]
#pragma unroll
        for (int q = 0; q < 2; q++) {
            int lin = tid + q * 256;
            int row = lin >> 2, c4 = lin & 3;
            float4 v = *reinterpret_cast<const float4*>(&X[(n0 + row) * E_DIM + kt + c4 * 4]);
            As[c4 * 4 + 0][row] = v.x;
            As[c4 * 4 + 1][row] = v.y;
            As[c4 * 4 + 2][row] = v.z;
            As[c4 * 4 + 3][row] = v.w;
        }
        // B tile 64x16 -> transposed + duplicated into Bsd[k][2f]
        {
            int row = tid >> 2, c4 = tid & 3;
            float4 v = *reinterpret_cast<const float4*>(&W[(f0 + row) * E_DIM + kt + c4 * 4]);
            Bsd[c4 * 4 + 0][2 * row] = v.x; Bsd[c4 * 4 + 0][2 * row + 1] = v.x;
            Bsd[c4 * 4 + 1][2 * row] = v.y; Bsd[c4 * 4 + 1][2 * row + 1] = v.y;
            Bsd[c4 * 4 + 2][2 * row] = v.z; Bsd[c4 * 4 + 2][2 * row + 1] = v.z;
            Bsd[c4 * 4 + 3][2 * row] = v.w; Bsd[c4 * 4 + 3][2 * row + 1] = v.w;
        }
        __syncthreads();
#pragma unroll
        for (int kk = 0; kk < 16; kk++) {
            const ulonglong2* ap = reinterpret_cast<const ulonglong2*>(&As[kk][ty * 8]);
            ulonglong2 A0 = ap[0], A1 = ap[1];
            u64 a2[4] = {A0.x, A0.y, A1.x, A1.y};
            const ulonglong2* bp = reinterpret_cast<const ulonglong2*>(&Bsd[kk][tx * 8]);
            ulonglong2 B0 = bp[0], B1 = bp[1];
            u64 b2[4] = {B0.x, B0.y, B1.x, B1.y};
#pragma unroll
            for (int i = 0; i < 4; i++)
#pragma unroll
                for (int j = 0; j < 4; j++) acc2[i][j] = ffma2(a2[i], b2[j], acc2[i][j]);
        }
        __syncthreads();
    }

    float4 bvv = *reinterpret_cast<const float4*>(&bias[f0 + tx * 4]);
    float bb[4] = {bvv.x, bvv.y, bvv.z, bvv.w};
    float acc[8][4];
#pragma unroll
    for (int i = 0; i < 4; i++)
#pragma unroll
        for (int j = 0; j < 4; j++) unpack2(acc2[i][j], acc[2 * i][j], acc[2 * i + 1][j]);
#pragma unroll
    for (int i = 0; i < 8; i++) {
        int n = n0 + ty * 8 + i;
        float r0 = acc[i][0] + bb[0];
        float r1 = acc[i][1] + bb[1];
        float r2 = acc[i][2] + bb[2];
        float r3 = acc[i][3] + bb[3];
        if (RELU) {
            r0 = fmaxf(r0, 0.f); r1 = fmaxf(r1, 0.f);
            r2 = fmaxf(r2, 0.f); r3 = fmaxf(r3, 0.f);
        }
        float4 o = make_float4(r0, r1, r2, r3);
        *reinterpret_cast<float4*>(&P[n * E_DIM + f0 + tx * 4]) = o;
    }
}

// ---------------------------------------------------------------------------
// Stage 2: dual KV-state GEMM (per batch) with FFMA2.
//   KVs[b][e][m] = sum_s sin(th_s) K[s,e] V[s,m];  KVc with cos.
// ---------------------------------------------------------------------------
__global__ __launch_bounds__(256)
void kv_kernel() {
    __shared__ __align__(16) float As[16][132];    // [s][e]
    __shared__ __align__(16) float Bsd[16][136];   // [s][2m] duplicated
    __shared__ __align__(16) u64 ssin2[16], scos2[16];

    const int b  = blockIdx.z;
    const int e0 = blockIdx.y * 128;
    const int m0 = blockIdx.x * 64;
    const int tid = threadIdx.x;
    const int ty = tid >> 4, tx = tid & 15;

    u64 accS[4][4], accC[4][4];
#pragma unroll
    for (int i = 0; i < 4; i++)
#pragma unroll
        for (int j = 0; j < 4; j++) { accS[i][j] = 0ULL; accC[i][j] = 0ULL; }

    for (int s0 = 0; s0 < S_DIM; s0 += 16) {
        if (tid < 16) {
            float th = HALF_PI * (float)(s0 + tid + 1) / (float)M_MAX;
            float sv = sinf(th), cv = cosf(th);
            ssin2[tid] = pack2(sv, sv);
            scos2[tid] = pack2(cv, cv);
        }
#pragma unroll
        for (int q = 0; q < 2; q++) {
            int lin = tid + q * 256;
            int ks = lin >> 5, f4 = lin & 31;
            float4 v = *reinterpret_cast<const float4*>(
                &g_Kp[((s0 + ks) * B_DIM + b) * E_DIM + e0 + f4 * 4]);
            *reinterpret_cast<float4*>(&As[ks][f4 * 4]) = v;
        }
        {
            int ks = tid >> 4, f4 = tid & 15;
            float4 v = *reinterpret_cast<const float4*>(
                &g_Vp[((s0 + ks) * B_DIM + b) * E_DIM + m0 + f4 * 4]);
            *reinterpret_cast<float4*>(&Bsd[ks][f4 * 8])     = make_float4(v.x, v.x, v.y, v.y);
            *reinterpret_cast<float4*>(&Bsd[ks][f4 * 8 + 4]) = make_float4(v.z, v.z, v.w, v.w);
        }
        __syncthreads();
#pragma unroll
        for (int kk = 0; kk < 16; kk++) {
            const ulonglong2* ap = reinterpret_cast<const ulonglong2*>(&As[kk][ty * 8]);
            ulonglong2 A0 = ap[0], A1 = ap[1];
            u64 a2[4] = {A0.x, A0.y, A1.x, A1.y};
            const ulonglong2* bp = reinterpret_cast<const ulonglong2*>(&Bsd[kk][tx * 8]);
            ulonglong2 B0 = bp[0], B1 = bp[1];
            u64 b2[4] = {B0.x, B0.y, B1.x, B1.y};
            u64 s2 = ssin2[kk], c2 = scos2[kk];
            u64 as2[4], ac2[4];
#pragma unroll
            for (int i = 0; i < 4; i++) { as2[i] = fmul2(a2[i], s2); ac2[i] = fmul2(a2[i], c2); }
#pragma unroll
            for (int i = 0; i < 4; i++)
#pragma unroll
                for (int j = 0; j < 4; j++) {
                    accS[i][j] = ffma2(as2[i], b2[j], accS[i][j]);
                    accC[i][j] = ffma2(ac2[i], b2[j], accC[i][j]);
                }
        }
        __syncthreads();
    }

    float aS[8][4], aC[8][4];
#pragma unroll
    for (int i = 0; i < 4; i++)
#pragma unroll
        for (int j = 0; j < 4; j++) {
            unpack2(accS[i][j], aS[2 * i][j], aS[2 * i + 1][j]);
            unpack2(accC[i][j], aC[2 * i][j], aC[2 * i + 1][j]);
        }
#pragma unroll
    for (int i = 0; i < 8; i++) {
        int e = e0 + ty * 8 + i;
        float4 os = make_float4(aS[i][0], aS[i][1], aS[i][2], aS[i][3]);
        float4 oc = make_float4(aC[i][0], aC[i][1], aC[i][2], aC[i][3]);
        *reinterpret_cast<float4*>(&g_KVs[(b * E_DIM + e) * E_DIM + m0 + tx * 4]) = os;
        *reinterpret_cast<float4*>(&g_KVc[(b * E_DIM + e) * E_DIM + m0 + tx * 4]) = oc;
    }
}

// ---------------------------------------------------------------------------
// Column sums: split over s into 16 chunks (256 blocks), partials + reduce.
// (Float atomics avoided -> bitwise deterministic.)
// ---------------------------------------------------------------------------
__global__ __launch_bounds__(256)
void colsum_kernel() {
    __shared__ float ssin[128], scos[128];
    const int idx = blockIdx.x * 256 + threadIdx.x;   // (b,e) flattened, 0..4095
    const int s0 = blockIdx.y * 128;
    if (threadIdx.x < 128) {
        float th = HALF_PI * (float)(s0 + threadIdx.x + 1) / (float)M_MAX;
        ssin[threadIdx.x] = sinf(th);
        scos[threadIdx.x] = cosf(th);
    }
    __syncthreads();
    float as = 0.f, ac = 0.f;
#pragma unroll 8
    for (int j = 0; j < 128; j++) {
        float v = g_Kp[(size_t)(s0 + j) * (B_DIM * E_DIM) + idx];
        as = fmaf(ssin[j], v, as);
        ac = fmaf(scos[j], v, ac);
    }
    g_KsP[blockIdx.y * (B_DIM * E_DIM) + idx] = as;
    g_KcP[blockIdx.y * (B_DIM * E_DIM) + idx] = ac;
}

__global__ __launch_bounds__(256)
void colsum_reduce_kernel() {
    const int idx = blockIdx.x * 256 + threadIdx.x;   // 0..4095
    float as = 0.f, ac = 0.f;
#pragma unroll
    for (int t = 0; t < 16; t++) {
        as += g_KsP[t * (B_DIM * E_DIM) + idx];
        ac += g_KcP[t * (B_DIM * E_DIM) + idx];
    }
    g_Ks[idx] = as;
    g_Kc[idx] = ac;
}

// ---------------------------------------------------------------------------
// Normalizer: Z[n] = 1/max( sin*dot(Qp,Ks) + cos*dot(Qp,Kc), eps )
// ---------------------------------------------------------------------------
__global__ __launch_bounds__(256)
void z_kernel() {
    const int warp = threadIdx.x >> 5, lane = threadIdx.x & 31;
    const int n = blockIdx.x * 8 + warp;
    const int b = n & 3, l = n >> 2;
    float ds = 0.f, dc = 0.f;
    for (int e = lane * 4; e < E_DIM; e += 128) {
        float4 q = *reinterpret_cast<const float4*>(&g_Qp[n * E_DIM + e]);
        float4 s = *reinterpret_cast<const float4*>(&g_Ks[b * E_DIM + e]);
        float4 c = *reinterpret_cast<const float4*>(&g_Kc[b * E_DIM + e]);
        ds += q.x * s.x + q.y * s.y + q.z * s.z + q.w * s.w;
        dc += q.x * c.x + q.y * c.y + q.z * c.z + q.w * c.w;
    }
#pragma unroll
    for (int o = 16; o; o >>= 1) {
        ds += __shfl_down_sync(0xFFFFFFFFu, ds, o);
        dc += __shfl_down_sync(0xFFFFFFFFu, dc, o);
    }
    if (lane == 0) {
        float th = HALF_PI * (float)(l + 1) / (float)M_MAX;
        float d = sinf(th) * ds + cosf(th) * dc;
        g_Z[n] = 1.0f / fmaxf(d, EPS_F);
    }
}

// ---------------------------------------------------------------------------
// Stage 3: output dual GEMM with FFMA2.
//   O[l,b,m] = Z * ( sin*Q@KVs + cos*Q@KVc )
// ---------------------------------------------------------------------------
__global__ __launch_bounds__(256)
void out_kernel(float* __restrict__ O) {
    __shared__ __align__(16) float As[16][132];     // [e][l], transposed
    __shared__ __align__(16) float Bssd[16][136];   // [e][2m] KVs duplicated
    __shared__ __align__(16) float Bscd[16][136];   // [e][2m] KVc duplicated

    const int b  = blockIdx.z;
    const int l0 = blockIdx.y * 128;
    const int m0 = blockIdx.x * 64;
    const int tid = threadIdx.x;
    const int ty = tid >> 4, tx = tid & 15;

    u64 accS[4][4], accC[4][4];
#pragma unroll
    for (int i = 0; i < 4; i++)
#pragma unroll
        for (int j = 0; j < 4; j++) { accS[i][j] = 0ULL; accC[i][j] = 0ULL; }

    for (int kt = 0; kt < E_DIM; kt += 16) {
#pragma unroll
        for (int q = 0; q < 2; q++) {
            int lin = tid + q * 256;
            int row = lin >> 2, c4 = lin & 3;
            float4 v = *reinterpret_cast<const float4*>(
                &g_Qp[((l0 + row) * B_DIM + b) * E_DIM + kt + c4 * 4]);
            As[c4 * 4 + 0][row] = v.x;
            As[c4 * 4 + 1][row] = v.y;
            As[c4 * 4 + 2][row] = v.z;
            As[c4 * 4 + 3][row] = v.w;
        }
        {
            int ks = tid >> 4, f4 = tid & 15;
            size_t base = ((size_t)b * E_DIM + (kt + ks)) * E_DIM + m0 + f4 * 4;
            float4 vs = *reinterpret_cast<const float4*>(&g_KVs[base]);
            float4 vc = *reinterpret_cast<const float4*>(&g_KVc[base]);
            *reinterpret_cast<float4*>(&Bssd[ks][f4 * 8])     = make_float4(vs.x, vs.x, vs.y, vs.y);
            *reinterpret_cast<float4*>(&Bssd[ks][f4 * 8 + 4]) = make_float4(vs.z, vs.z, vs.w, vs.w);
            *reinterpret_cast<float4*>(&Bscd[ks][f4 * 8])     = make_float4(vc.x, vc.x, vc.y, vc.y);
            *reinterpret_cast<float4*>(&Bscd[ks][f4 * 8 + 4]) = make_float4(vc.z, vc.z, vc.w, vc.w);
        }
        __syncthreads();
#pragma unroll
        for (int kk = 0; kk < 16; kk++) {
            const ulonglong2* ap = reinterpret_cast<const ulonglong2*>(&As[kk][ty * 8]);
            ulonglong2 A0 = ap[0], A1 = ap[1];
            u64 a2[4] = {A0.x, A0.y, A1.x, A1.y};
            const ulonglong2* bsp = reinterpret_cast<const ulonglong2*>(&Bssd[kk][tx * 8]);
            ulonglong2 S0 = bsp[0], S1 = bsp[1];
            u64 bs2[4] = {S0.x, S0.y, S1.x, S1.y};
            const ulonglong2* bcp = reinterpret_cast<const ulonglong2*>(&Bscd[kk][tx * 8]);
            ulonglong2 C0 = bcp[0], C1 = bcp[1];
            u64 bc2[4] = {C0.x, C0.y, C1.x, C1.y};
#pragma unroll
            for (int i = 0; i < 4; i++)
#pragma unroll
                for (int j = 0; j < 4; j++) {
                    accS[i][j] = ffma2(a2[i], bs2[j], accS[i][j]);
                    accC[i][j] = ffma2(a2[i], bc2[j], accC[i][j]);
                }
        }
        __syncthreads();
    }

    float aS[8][4], aC[8][4];
#pragma unroll
    for (int i = 0; i < 4; i++)
#pragma unroll
        for (int j = 0; j < 4; j++) {
            unpack2(accS[i][j], aS[2 * i][j], aS[2 * i + 1][j]);
            unpack2(accC[i][j], aC[2 * i][j], aC[2 * i + 1][j]);
        }
#pragma unroll
    for (int i = 0; i < 8; i++) {
        int l = l0 + ty * 8 + i;
        float th = HALF_PI * (float)(l + 1) / (float)M_MAX;
        float sl = sinf(th), cl = cosf(th);
        float zz = g_Z[l * B_DIM + b];
        float4 o;
        o.x = zz * (sl * aS[i][0] + cl * aC[i][0]);
        o.y = zz * (sl * aS[i][1] + cl * aC[i][1]);
        o.z = zz * (sl * aS[i][2] + cl * aC[i][2]);
        o.w = zz * (sl * aS[i][3] + cl * aC[i][3]);
        *reinterpret_cast<float4*>(&O[((size_t)l * B_DIM + b) * E_DIM + m0 + tx * 4]) = o;
    }
}

// ---------------------------------------------------------------------------
// Launch
// ---------------------------------------------------------------------------
extern "C" void kernel_launch(void* const* d_in, const int* in_sizes, int n_in,
                              void* d_out, int out_size) {
    const float* query = (const float*)d_in[0];
    const float* key   = (const float*)d_in[1];
    const float* value = (const float*)d_in[2];
    const float* Wq    = (const float*)d_in[3];
    const float* bq    = (const float*)d_in[4];
    const float* Wk    = (const float*)d_in[5];
    const float* bk    = (const float*)d_in[6];
    const float* Wv    = (const float*)d_in[7];
    const float* bv    = (const float*)d_in[8];
    float* out = (float*)d_out;

    float *pQ, *pK, *pV;
    cudaGetSymbolAddress((void**)&pQ, g_Qp);
    cudaGetSymbolAddress((void**)&pK, g_Kp);
    cudaGetSymbolAddress((void**)&pV, g_Vp);

    dim3 projGrid(E_DIM / 64, N_ROWS / 128);   // (16, 64)
    proj_kernel<true><<<projGrid, 256>>>(query, Wq, bq, pQ);
    proj_kernel<true><<<projGrid, 256>>>(key,   Wk, bk, pK);
    proj_kernel<false><<<projGrid, 256>>>(value, Wv, bv, pV);

    dim3 csGrid(16, 16);
    colsum_kernel<<<csGrid, 256>>>();
    colsum_reduce_kernel<<<16, 256>>>();

    dim3 kvGrid(E_DIM / 64, E_DIM / 128, B_DIM);   // (16, 8, 4)
    kv_kernel<<<kvGrid, 256>>>();

    z_kernel<<<N_ROWS / 8, 256>>>();

    dim3 outGrid(E_DIM / 64, L_DIM / 128, B_DIM);  // (16, 16, 4)
    out_kernel<<<outGrid, 256>>>(out);
}

// round 4
// speedup vs baseline: 2.7081x; 2.7081x over previous
#include <cuda_runtime.h>
#include <cuda_bf16.h>
#include <math.h>

#define L_DIM 2048
#define B_DIM 4
#define E_DIM 1024
#define N_ROWS 8192
#define HALF_PI 1.5707963267948966f
#define EPS_F 1e-6f

typedef __nv_bfloat16 bf16;
typedef __nv_bfloat162 bf162;

// ---------------------------------------------------------------------------
// Scratch (__device__ globals; no allocation allowed)
// ---------------------------------------------------------------------------
#define NE (N_ROWS * E_DIM)       // 8388608
#define WE (E_DIM * E_DIM)        // 1048576
#define KVN (B_DIM * E_DIM * E_DIM)

__device__ bf16 g_sq_hi[NE], g_sq_lo[NE];
__device__ bf16 g_sk_hi[NE], g_sk_lo[NE];
__device__ bf16 g_sv_hi[NE], g_sv_lo[NE];
__device__ bf16 g_wq_hi[WE], g_wq_lo[WE];
__device__ bf16 g_wk_hi[WE], g_wk_lo[WE];
__device__ bf16 g_wv_hi[WE], g_wv_lo[WE];

__device__ bf16 g_Qp_hi[NE], g_Qp_lo[NE];
__device__ bf16 g_Ksin_hi[NE], g_Ksin_lo[NE];   // sin(th_s)*relu(K proj), split
__device__ bf16 g_Kcos_hi[NE], g_Kcos_lo[NE];
__device__ bf16 g_Vp_hi[NE], g_Vp_lo[NE];

__device__ bf16 g_KVs_hi[KVN], g_KVs_lo[KVN];   // [b][e][m]
__device__ bf16 g_KVc_hi[KVN], g_KVc_lo[KVN];

__device__ float g_Ks[B_DIM * E_DIM];
__device__ float g_Kc[B_DIM * E_DIM];
__device__ float g_KsP[16 * B_DIM * E_DIM];
__device__ float g_KcP[16 * B_DIM * E_DIM];
__device__ float g_Z[N_ROWS];

// ---------------------------------------------------------------------------
// MMA / ldmatrix helpers
// ---------------------------------------------------------------------------
__device__ __forceinline__ unsigned smem_u32(const void* p) {
    return (unsigned)__cvta_generic_to_shared(p);
}
__device__ __forceinline__ void ldsm4(unsigned a, unsigned& r0, unsigned& r1,
                                      unsigned& r2, unsigned& r3) {
    asm volatile("ldmatrix.sync.aligned.m8n8.x4.shared.b16 {%0,%1,%2,%3},[%4];"
                 : "=r"(r0), "=r"(r1), "=r"(r2), "=r"(r3) : "r"(a));
}
__device__ __forceinline__ void ldsm4t(unsigned a, unsigned& r0, unsigned& r1,
                                       unsigned& r2, unsigned& r3) {
    asm volatile("ldmatrix.sync.aligned.m8n8.x4.trans.shared.b16 {%0,%1,%2,%3},[%4];"
                 : "=r"(r0), "=r"(r1), "=r"(r2), "=r"(r3) : "r"(a));
}
__device__ __forceinline__ void mma16816(float* c, const unsigned* a, const unsigned* b) {
    asm volatile(
        "mma.sync.aligned.m16n8k16.row.col.f32.bf16.bf16.f32 "
        "{%0,%1,%2,%3},{%4,%5,%6,%7},{%8,%9},{%0,%1,%2,%3};"
        : "+f"(c[0]), "+f"(c[1]), "+f"(c[2]), "+f"(c[3])
        : "r"(a[0]), "r"(a[1]), "r"(a[2]), "r"(a[3]), "r"(b[0]), "r"(b[1]));
}
__device__ __forceinline__ void split1(float v, bf16& h, bf16& l) {
    h = __float2bfloat16(v);
    l = __float2bfloat16(v - __bfloat162float(h));
}
__device__ __forceinline__ void store_split2(bf16* hi, bf16* lo, size_t idx,
                                             float v0, float v1) {
    bf16 h0, l0, h1, l1;
    split1(v0, h0, l0);
    split1(v1, h1, l1);
    bf162 th; th.x = h0; th.y = h1;
    bf162 tl; tl.x = l0; tl.y = l1;
    *reinterpret_cast<bf162*>(hi + idx) = th;
    *reinterpret_cast<bf162*>(lo + idx) = tl;
}

// ---------------------------------------------------------------------------
// Split fp32 -> bf16 hi/lo
// ---------------------------------------------------------------------------
__global__ __launch_bounds__(256)
void split_kernel(const float* __restrict__ x, bf16* __restrict__ hi,
                  bf16* __restrict__ lo, int n4) {
    int i = blockIdx.x * 256 + threadIdx.x;
    if (i >= n4) return;
    float4 v = reinterpret_cast<const float4*>(x)[i];
    bf16 h0, l0, h1, l1, h2, l2, h3, l3;
    split1(v.x, h0, l0); split1(v.y, h1, l1);
    split1(v.z, h2, l2); split1(v.w, h3, l3);
    bf162 a, b, c, d;
    a.x = h0; a.y = h1; b.x = h2; b.y = h3;
    c.x = l0; c.y = l1; d.x = l2; d.y = l3;
    reinterpret_cast<bf162*>(hi)[2 * i] = a;
    reinterpret_cast<bf162*>(hi)[2 * i + 1] = b;
    reinterpret_cast<bf162*>(lo)[2 * i] = c;
    reinterpret_cast<bf162*>(lo)[2 * i + 1] = d;
}

// ---------------------------------------------------------------------------
// Stage 1: projection GEMM (tensor). C[m,n] = sum_k A[m,k]*W[n,k] + bias, act.
// Block 128x64, 8 warps (4x2), warp 32x32. MODE: 0=Q (relu), 1=K (relu +
// sin/cos scaled split outputs), 2=V (no relu).
// ---------------------------------------------------------------------------
template <int MODE>
__global__ __launch_bounds__(256)
void proj_mma(const bf16* __restrict__ Ah_g, const bf16* __restrict__ Al_g,
              const bf16* __restrict__ Bh_g, const bf16* __restrict__ Bl_g,
              const float* __restrict__ bias,
              bf16* __restrict__ O1h, bf16* __restrict__ O1l,
              bf16* __restrict__ O2h, bf16* __restrict__ O2l) {
    __shared__ bf16 Ah[128][24], Al[128][24];
    __shared__ bf16 Bh[64][24], Bl[64][24];

    const int tid = threadIdx.x, lane = tid & 31, w = tid >> 5;
    const int wm = (w & 3) * 32, wn = (w >> 2) * 32;
    const int m0 = blockIdx.y * 128, n0 = blockIdx.x * 64;

    const int ar = tid >> 1, ac = (tid & 1) * 8;
    const int br = tid >> 2, bc = (tid & 3) * 4;

    float c[2][4][4];
#pragma unroll
    for (int i = 0; i < 2; i++)
#pragma unroll
        for (int j = 0; j < 4; j++)
#pragma unroll
            for (int q = 0; q < 4; q++) c[i][j][q] = 0.f;

    for (int kt = 0; kt < E_DIM; kt += 16) {
        __syncthreads();
        *reinterpret_cast<uint4*>(&Ah[ar][ac]) =
            *reinterpret_cast<const uint4*>(&Ah_g[(size_t)(m0 + ar) * E_DIM + kt + ac]);
        *reinterpret_cast<uint4*>(&Al[ar][ac]) =
            *reinterpret_cast<const uint4*>(&Al_g[(size_t)(m0 + ar) * E_DIM + kt + ac]);
        *reinterpret_cast<uint2*>(&Bh[br][bc]) =
            *reinterpret_cast<const uint2*>(&Bh_g[(size_t)(n0 + br) * E_DIM + kt + bc]);
        *reinterpret_cast<uint2*>(&Bl[br][bc]) =
            *reinterpret_cast<const uint2*>(&Bl_g[(size_t)(n0 + br) * E_DIM + kt + bc]);
        __syncthreads();

        unsigned ah[2][4], al[2][4], bh[4][2], bl[4][2];
#pragma unroll
        for (int fi = 0; fi < 2; fi++) {
            unsigned aadr = smem_u32(&Ah[wm + fi * 16 + (lane & 15)][(lane >> 4) * 8]);
            ldsm4(aadr, ah[fi][0], ah[fi][1], ah[fi][2], ah[fi][3]);
            unsigned aadr2 = smem_u32(&Al[wm + fi * 16 + (lane & 15)][(lane >> 4) * 8]);
            ldsm4(aadr2, al[fi][0], al[fi][1], al[fi][2], al[fi][3]);
        }
#pragma unroll
        for (int g = 0; g < 2; g++) {
            int nrow = wn + g * 16 + (lane >> 4) * 8 + (lane & 7);
            int kcol = ((lane >> 3) & 1) * 8;
            unsigned badr = smem_u32(&Bh[nrow][kcol]);
            ldsm4(badr, bh[2 * g][0], bh[2 * g][1], bh[2 * g + 1][0], bh[2 * g + 1][1]);
            unsigned badr2 = smem_u32(&Bl[nrow][kcol]);
            ldsm4(badr2, bl[2 * g][0], bl[2 * g][1], bl[2 * g + 1][0], bl[2 * g + 1][1]);
        }
#pragma unroll
        for (int fi = 0; fi < 2; fi++)
#pragma unroll
            for (int fj = 0; fj < 4; fj++) {
                mma16816(c[fi][fj], ah[fi], bh[fj]);
                mma16816(c[fi][fj], ah[fi], bl[fj]);
                mma16816(c[fi][fj], al[fi], bh[fj]);
            }
    }

    const int row = lane >> 2, col2 = (lane & 3) * 2;
#pragma unroll
    for (int fi = 0; fi < 2; fi++)
#pragma unroll
        for (int h = 0; h < 2; h++) {
            int m = m0 + wm + fi * 16 + row + h * 8;
            float th = 0.f, sl = 0.f, cl = 0.f;
            if (MODE == 1) {
                th = HALF_PI * (float)((m >> 2) + 1) * (1.0f / 2048.0f);
                sl = sinf(th); cl = cosf(th);
            }
#pragma unroll
            for (int fj = 0; fj < 4; fj++) {
                int n = n0 + wn + fj * 8 + col2;
                float v0 = c[fi][fj][h * 2 + 0] + bias[n];
                float v1 = c[fi][fj][h * 2 + 1] + bias[n + 1];
                if (MODE != 2) { v0 = fmaxf(v0, 0.f); v1 = fmaxf(v1, 0.f); }
                size_t idx = (size_t)m * E_DIM + n;
                if (MODE == 1) {
                    store_split2(O1h, O1l, idx, sl * v0, sl * v1);
                    store_split2(O2h, O2l, idx, cl * v0, cl * v1);
                } else {
                    store_split2(O1h, O1l, idx, v0, v1);
                }
            }
        }
}

// ---------------------------------------------------------------------------
// Stage 2: dual KV-state GEMM (per batch, tensor).
//   KVs[b][e][m] = sum_s Ksin[s,b,e] * Vp[s,b,m]   (Kcos -> KVc)
// A tiles [k=s][m=e] (trans ldmatrix), B tiles [k=s][n=m] (trans ldmatrix).
// ---------------------------------------------------------------------------
__global__ __launch_bounds__(256)
void kv_mma() {
    __shared__ bf16 Ash[16][136], Asl[16][136], Ach[16][136], Acl[16][136];
    __shared__ bf16 Bh[16][72], Bl[16][72];

    const int tid = threadIdx.x, lane = tid & 31, w = tid >> 5;
    const int wm = (w & 3) * 32, wn = (w >> 2) * 32;
    const int b = blockIdx.z;
    const int e0 = blockIdx.y * 128, n0 = blockIdx.x * 64;

    const int asr = tid >> 4, asc = (tid & 15) * 8;
    const int bsr = tid >> 4, bsc = (tid & 15) * 4;

    float cs[2][4][4], cc[2][4][4];
#pragma unroll
    for (int i = 0; i < 2; i++)
#pragma unroll
        for (int j = 0; j < 4; j++)
#pragma unroll
            for (int q = 0; q < 4; q++) { cs[i][j][q] = 0.f; cc[i][j][q] = 0.f; }

    for (int s0 = 0; s0 < L_DIM; s0 += 16) {
        __syncthreads();
        size_t ga = ((size_t)(s0 + asr) * B_DIM + b) * E_DIM + e0 + asc;
        *reinterpret_cast<uint4*>(&Ash[asr][asc]) = *reinterpret_cast<const uint4*>(&g_Ksin_hi[ga]);
        *reinterpret_cast<uint4*>(&Asl[asr][asc]) = *reinterpret_cast<const uint4*>(&g_Ksin_lo[ga]);
        *reinterpret_cast<uint4*>(&Ach[asr][asc]) = *reinterpret_cast<const uint4*>(&g_Kcos_hi[ga]);
        *reinterpret_cast<uint4*>(&Acl[asr][asc]) = *reinterpret_cast<const uint4*>(&g_Kcos_lo[ga]);
        size_t gb = ((size_t)(s0 + bsr) * B_DIM + b) * E_DIM + n0 + bsc;
        *reinterpret_cast<uint2*>(&Bh[bsr][bsc]) = *reinterpret_cast<const uint2*>(&g_Vp_hi[gb]);
        *reinterpret_cast<uint2*>(&Bl[bsr][bsc]) = *reinterpret_cast<const uint2*>(&g_Vp_lo[gb]);
        __syncthreads();

        unsigned bhf[4][2], blf[4][2];
        {
            int krow = ((lane >> 3) & 1) * 8 + (lane & 7);
#pragma unroll
            for (int g = 0; g < 2; g++) {
                int ncol = wn + g * 16 + (lane >> 4) * 8;
                unsigned a1 = smem_u32(&Bh[krow][ncol]);
                ldsm4t(a1, bhf[2 * g][0], bhf[2 * g][1], bhf[2 * g + 1][0], bhf[2 * g + 1][1]);
                unsigned a2 = smem_u32(&Bl[krow][ncol]);
                ldsm4t(a2, blf[2 * g][0], blf[2 * g][1], blf[2 * g + 1][0], blf[2 * g + 1][1]);
            }
        }
#pragma unroll
        for (int fi = 0; fi < 2; fi++) {
            int krow = (lane & 7) + (lane >> 4) * 8;
            int mcol = wm + fi * 16 + ((lane >> 3) & 1) * 8;
            unsigned ash[4], asl_[4], ach[4], acl_[4];
            ldsm4t(smem_u32(&Ash[krow][mcol]), ash[0], ash[1], ash[2], ash[3]);
            ldsm4t(smem_u32(&Asl[krow][mcol]), asl_[0], asl_[1], asl_[2], asl_[3]);
            ldsm4t(smem_u32(&Ach[krow][mcol]), ach[0], ach[1], ach[2], ach[3]);
            ldsm4t(smem_u32(&Acl[krow][mcol]), acl_[0], acl_[1], acl_[2], acl_[3]);
#pragma unroll
            for (int fj = 0; fj < 4; fj++) {
                mma16816(cs[fi][fj], ash, bhf[fj]);
                mma16816(cs[fi][fj], ash, blf[fj]);
                mma16816(cs[fi][fj], asl_, bhf[fj]);
                mma16816(cc[fi][fj], ach, bhf[fj]);
                mma16816(cc[fi][fj], ach, blf[fj]);
                mma16816(cc[fi][fj], acl_, bhf[fj]);
            }
        }
    }

    const int row = lane >> 2, col2 = (lane & 3) * 2;
#pragma unroll
    for (int fi = 0; fi < 2; fi++)
#pragma unroll
        for (int h = 0; h < 2; h++) {
            int e = e0 + wm + fi * 16 + row + h * 8;
#pragma unroll
            for (int fj = 0; fj < 4; fj++) {
                int m = n0 + wn + fj * 8 + col2;
                size_t idx = ((size_t)b * E_DIM + e) * E_DIM + m;
                store_split2(g_KVs_hi, g_KVs_lo, idx, cs[fi][fj][h * 2], cs[fi][fj][h * 2 + 1]);
                store_split2(g_KVc_hi, g_KVc_lo, idx, cc[fi][fj][h * 2], cc[fi][fj][h * 2 + 1]);
            }
        }
}

// ---------------------------------------------------------------------------
// Column sums of the sin/cos-scaled K (scaling already baked in).
// ---------------------------------------------------------------------------
__global__ __launch_bounds__(256)
void colsum_kernel() {
    const int idx = blockIdx.x * 256 + threadIdx.x;   // b*E + e
    const int s0 = blockIdx.y * 128;
    float as = 0.f, ac = 0.f;
#pragma unroll 4
    for (int j = 0; j < 128; j++) {
        size_t g = (size_t)(s0 + j) * (B_DIM * E_DIM) + idx;
        as += __bfloat162float(g_Ksin_hi[g]) + __bfloat162float(g_Ksin_lo[g]);
        ac += __bfloat162float(g_Kcos_hi[g]) + __bfloat162float(g_Kcos_lo[g]);
    }
    g_KsP[blockIdx.y * (B_DIM * E_DIM) + idx] = as;
    g_KcP[blockIdx.y * (B_DIM * E_DIM) + idx] = ac;
}

__global__ __launch_bounds__(256)
void colsum_reduce_kernel() {
    const int idx = blockIdx.x * 256 + threadIdx.x;
    float as = 0.f, ac = 0.f;
#pragma unroll
    for (int t = 0; t < 16; t++) {
        as += g_KsP[t * (B_DIM * E_DIM) + idx];
        ac += g_KcP[t * (B_DIM * E_DIM) + idx];
    }
    g_Ks[idx] = as;
    g_Kc[idx] = ac;
}

// ---------------------------------------------------------------------------
// Normalizer Z[n] = 1/max( dot(Qp[n], Ks[b])*sin_l + dot(Qp[n], Kc[b])*cos_l, eps )
// ---------------------------------------------------------------------------
__global__ __launch_bounds__(256)
void z_kernel() {
    const int warp = threadIdx.x >> 5, lane = threadIdx.x & 31;
    const int n = blockIdx.x * 8 + warp;
    const int b = n & 3, l = n >> 2;
    float ds = 0.f, dc = 0.f;
    for (int e = lane * 8; e < E_DIM; e += 256) {
        uint4 qh = *reinterpret_cast<const uint4*>(&g_Qp_hi[(size_t)n * E_DIM + e]);
        uint4 ql = *reinterpret_cast<const uint4*>(&g_Qp_lo[(size_t)n * E_DIM + e]);
        const bf162* ph = reinterpret_cast<const bf162*>(&qh);
        const bf162* pl = reinterpret_cast<const bf162*>(&ql);
        float q[8];
#pragma unroll
        for (int i = 0; i < 4; i++) {
            q[2 * i]     = __bfloat162float(ph[i].x) + __bfloat162float(pl[i].x);
            q[2 * i + 1] = __bfloat162float(ph[i].y) + __bfloat162float(pl[i].y);
        }
        float4 k0 = *reinterpret_cast<const float4*>(&g_Ks[b * E_DIM + e]);
        float4 k1 = *reinterpret_cast<const float4*>(&g_Ks[b * E_DIM + e + 4]);
        float4 c0 = *reinterpret_cast<const float4*>(&g_Kc[b * E_DIM + e]);
        float4 c1 = *reinterpret_cast<const float4*>(&g_Kc[b * E_DIM + e + 4]);
        ds += q[0]*k0.x + q[1]*k0.y + q[2]*k0.z + q[3]*k0.w
            + q[4]*k1.x + q[5]*k1.y + q[6]*k1.z + q[7]*k1.w;
        dc += q[0]*c0.x + q[1]*c0.y + q[2]*c0.z + q[3]*c0.w
            + q[4]*c1.x + q[5]*c1.y + q[6]*c1.z + q[7]*c1.w;
    }
#pragma unroll
    for (int o = 16; o; o >>= 1) {
        ds += __shfl_down_sync(0xFFFFFFFFu, ds, o);
        dc += __shfl_down_sync(0xFFFFFFFFu, dc, o);
    }
    if (lane == 0) {
        float th = HALF_PI * (float)(l + 1) * (1.0f / 2048.0f);
        float d = sinf(th) * ds + cosf(th) * dc;
        g_Z[n] = 1.0f / fmaxf(d, EPS_F);
    }
}

// ---------------------------------------------------------------------------
// Stage 3: output dual GEMM (per batch, tensor).
//   O[l,b,m] = Z * ( sin_l * Qp@KVs[b] + cos_l * Qp@KVc[b] )
// A = Qp rows (l,b) [m][k] non-trans; B = KV [k=e][n=m] trans.
// ---------------------------------------------------------------------------
__global__ __launch_bounds__(256)
void out_mma(float* __restrict__ O) {
    __shared__ bf16 Ah[128][24], Al[128][24];
    __shared__ bf16 Bsh[16][72], Bsl[16][72], Bch[16][72], Bcl[16][72];

    const int tid = threadIdx.x, lane = tid & 31, w = tid >> 5;
    const int wm = (w & 3) * 32, wn = (w >> 2) * 32;
    const int b = blockIdx.z;
    const int l0 = blockIdx.y * 128, n0 = blockIdx.x * 64;

    const int ar = tid >> 1, ac = (tid & 1) * 8;
    const int bsr = tid >> 4, bsc = (tid & 15) * 4;

    float cs[2][4][4], cc[2][4][4];
#pragma unroll
    for (int i = 0; i < 2; i++)
#pragma unroll
        for (int j = 0; j < 4; j++)
#pragma unroll
            for (int q = 0; q < 4; q++) { cs[i][j][q] = 0.f; cc[i][j][q] = 0.f; }

    for (int kt = 0; kt < E_DIM; kt += 16) {
        __syncthreads();
        size_t ga = ((size_t)(l0 + ar) * B_DIM + b) * E_DIM + kt + ac;
        *reinterpret_cast<uint4*>(&Ah[ar][ac]) = *reinterpret_cast<const uint4*>(&g_Qp_hi[ga]);
        *reinterpret_cast<uint4*>(&Al[ar][ac]) = *reinterpret_cast<const uint4*>(&g_Qp_lo[ga]);
        size_t gb = ((size_t)b * E_DIM + kt + bsr) * E_DIM + n0 + bsc;
        *reinterpret_cast<uint2*>(&Bsh[bsr][bsc]) = *reinterpret_cast<const uint2*>(&g_KVs_hi[gb]);
        *reinterpret_cast<uint2*>(&Bsl[bsr][bsc]) = *reinterpret_cast<const uint2*>(&g_KVs_lo[gb]);
        *reinterpret_cast<uint2*>(&Bch[bsr][bsc]) = *reinterpret_cast<const uint2*>(&g_KVc_hi[gb]);
        *reinterpret_cast<uint2*>(&Bcl[bsr][bsc]) = *reinterpret_cast<const uint2*>(&g_KVc_lo[gb]);
        __syncthreads();

        unsigned bsh[4][2], bsl_[4][2], bch[4][2], bcl_[4][2];
        {
            int krow = ((lane >> 3) & 1) * 8 + (lane & 7);
#pragma unroll
            for (int g = 0; g < 2; g++) {
                int ncol = wn + g * 16 + (lane >> 4) * 8;
                ldsm4t(smem_u32(&Bsh[krow][ncol]), bsh[2*g][0], bsh[2*g][1], bsh[2*g+1][0], bsh[2*g+1][1]);
                ldsm4t(smem_u32(&Bsl[krow][ncol]), bsl_[2*g][0], bsl_[2*g][1], bsl_[2*g+1][0], bsl_[2*g+1][1]);
                ldsm4t(smem_u32(&Bch[krow][ncol]), bch[2*g][0], bch[2*g][1], bch[2*g+1][0], bch[2*g+1][1]);
                ldsm4t(smem_u32(&Bcl[krow][ncol]), bcl_[2*g][0], bcl_[2*g][1], bcl_[2*g+1][0], bcl_[2*g+1][1]);
            }
        }
#pragma unroll
        for (int fi = 0; fi < 2; fi++) {
            unsigned ah[4], al_[4];
            unsigned aadr = smem_u32(&Ah[wm + fi * 16 + (lane & 15)][(lane >> 4) * 8]);
            ldsm4(aadr, ah[0], ah[1], ah[2], ah[3]);
            unsigned aadr2 = smem_u32(&Al[wm + fi * 16 + (lane & 15)][(lane >> 4) * 8]);
            ldsm4(aadr2, al_[0], al_[1], al_[2], al_[3]);
#pragma unroll
            for (int fj = 0; fj < 4; fj++) {
                mma16816(cs[fi][fj], ah, bsh[fj]);
                mma16816(cs[fi][fj], ah, bsl_[fj]);
                mma16816(cs[fi][fj], al_, bsh[fj]);
                mma16816(cc[fi][fj], ah, bch[fj]);
                mma16816(cc[fi][fj], ah, bcl_[fj]);
                mma16816(cc[fi][fj], al_, bch[fj]);
            }
        }
    }

    const int row = lane >> 2, col2 = (lane & 3) * 2;
#pragma unroll
    for (int fi = 0; fi < 2; fi++)
#pragma unroll
        for (int h = 0; h < 2; h++) {
            int l = l0 + wm + fi * 16 + row + h * 8;
            float th = HALF_PI * (float)(l + 1) * (1.0f / 2048.0f);
            float sl = sinf(th), cl = cosf(th);
            float zz = g_Z[l * B_DIM + b];
#pragma unroll
            for (int fj = 0; fj < 4; fj++) {
                int n = n0 + wn + fj * 8 + col2;
                float2 o;
                o.x = zz * (sl * cs[fi][fj][h * 2]     + cl * cc[fi][fj][h * 2]);
                o.y = zz * (sl * cs[fi][fj][h * 2 + 1] + cl * cc[fi][fj][h * 2 + 1]);
                *reinterpret_cast<float2*>(&O[((size_t)l * B_DIM + b) * E_DIM + n]) = o;
            }
        }
}

// ---------------------------------------------------------------------------
// Launch
// ---------------------------------------------------------------------------
extern "C" void kernel_launch(void* const* d_in, const int* in_sizes, int n_in,
                              void* d_out, int out_size) {
    const float* query = (const float*)d_in[0];
    const float* key   = (const float*)d_in[1];
    const float* value = (const float*)d_in[2];
    const float* Wq    = (const float*)d_in[3];
    const float* bq    = (const float*)d_in[4];
    const float* Wk    = (const float*)d_in[5];
    const float* bk    = (const float*)d_in[6];
    const float* Wv    = (const float*)d_in[7];
    const float* bv    = (const float*)d_in[8];
    float* out = (float*)d_out;

    bf16 *sq_hi, *sq_lo, *sk_hi, *sk_lo, *sv_hi, *sv_lo;
    bf16 *wq_hi, *wq_lo, *wk_hi, *wk_lo, *wv_hi, *wv_lo;
    bf16 *Qp_hi, *Qp_lo, *Ksin_hi, *Ksin_lo, *Kcos_hi, *Kcos_lo, *Vp_hi, *Vp_lo;
    cudaGetSymbolAddress((void**)&sq_hi, g_sq_hi);
    cudaGetSymbolAddress((void**)&sq_lo, g_sq_lo);
    cudaGetSymbolAddress((void**)&sk_hi, g_sk_hi);
    cudaGetSymbolAddress((void**)&sk_lo, g_sk_lo);
    cudaGetSymbolAddress((void**)&sv_hi, g_sv_hi);
    cudaGetSymbolAddress((void**)&sv_lo, g_sv_lo);
    cudaGetSymbolAddress((void**)&wq_hi, g_wq_hi);
    cudaGetSymbolAddress((void**)&wq_lo, g_wq_lo);
    cudaGetSymbolAddress((void**)&wk_hi, g_wk_hi);
    cudaGetSymbolAddress((void**)&wk_lo, g_wk_lo);
    cudaGetSymbolAddress((void**)&wv_hi, g_wv_hi);
    cudaGetSymbolAddress((void**)&wv_lo, g_wv_lo);
    cudaGetSymbolAddress((void**)&Qp_hi, g_Qp_hi);
    cudaGetSymbolAddress((void**)&Qp_lo, g_Qp_lo);
    cudaGetSymbolAddress((void**)&Ksin_hi, g_Ksin_hi);
    cudaGetSymbolAddress((void**)&Ksin_lo, g_Ksin_lo);
    cudaGetSymbolAddress((void**)&Kcos_hi, g_Kcos_hi);
    cudaGetSymbolAddress((void**)&Kcos_lo, g_Kcos_lo);
    cudaGetSymbolAddress((void**)&Vp_hi, g_Vp_hi);
    cudaGetSymbolAddress((void**)&Vp_lo, g_Vp_lo);

    // Split inputs to bf16 hi/lo
    split_kernel<<<NE / 4 / 256, 256>>>(query, sq_hi, sq_lo, NE / 4);
    split_kernel<<<NE / 4 / 256, 256>>>(key,   sk_hi, sk_lo, NE / 4);
    split_kernel<<<NE / 4 / 256, 256>>>(value, sv_hi, sv_lo, NE / 4);
    split_kernel<<<WE / 4 / 256, 256>>>(Wq, wq_hi, wq_lo, WE / 4);
    split_kernel<<<WE / 4 / 256, 256>>>(Wk, wk_hi, wk_lo, WE / 4);
    split_kernel<<<WE / 4 / 256, 256>>>(Wv, wv_hi, wv_lo, WE / 4);

    // Projections (tensor)
    dim3 projGrid(E_DIM / 64, N_ROWS / 128);   // (16, 64)
    proj_mma<0><<<projGrid, 256>>>(sq_hi, sq_lo, wq_hi, wq_lo, bq,
                                   Qp_hi, Qp_lo, nullptr, nullptr);
    proj_mma<1><<<projGrid, 256>>>(sk_hi, sk_lo, wk_hi, wk_lo, bk,
                                   Ksin_hi, Ksin_lo, Kcos_hi, Kcos_lo);
    proj_mma<2><<<projGrid, 256>>>(sv_hi, sv_lo, wv_hi, wv_lo, bv,
                                   Vp_hi, Vp_lo, nullptr, nullptr);

    // Column sums + normalizer
    dim3 csGrid(16, 16);
    colsum_kernel<<<csGrid, 256>>>();
    colsum_reduce_kernel<<<16, 256>>>();
    z_kernel<<<N_ROWS / 8, 256>>>();

    // KV state (tensor, dual)
    dim3 kvGrid(E_DIM / 64, E_DIM / 128, B_DIM);   // (16, 8, 4)
    kv_mma<<<kvGrid, 256>>>();

    // Output (tensor, dual)
    dim3 outGrid(E_DIM / 64, L_DIM / 128, B_DIM);  // (16, 16, 4)
    out_mma<<<outGrid, 256>>>(out);
}

// round 5
// speedup vs baseline: 3.5705x; 1.3184x over previous
#include <cuda_runtime.h>
#include <cuda_bf16.h>
#include <math.h>

#define L_DIM 2048
#define B_DIM 4
#define E_DIM 1024
#define N_ROWS 8192
#define HALF_PI 1.5707963267948966f
#define EPS_F 1e-6f

typedef __nv_bfloat16 bf16;
typedef __nv_bfloat162 bf162;

#define NE (N_ROWS * E_DIM)
#define WE (E_DIM * E_DIM)
#define KVN (B_DIM * E_DIM * E_DIM)

__device__ bf16 g_sq_hi[NE], g_sq_lo[NE];
__device__ bf16 g_sk_hi[NE], g_sk_lo[NE];
__device__ bf16 g_sv_hi[NE], g_sv_lo[NE];
__device__ bf16 g_wq_hi[WE], g_wq_lo[WE];
__device__ bf16 g_wk_hi[WE], g_wk_lo[WE];
__device__ bf16 g_wv_hi[WE], g_wv_lo[WE];

__device__ bf16 g_Qp_hi[NE], g_Qp_lo[NE];
__device__ bf16 g_Ksin_hi[NE], g_Ksin_lo[NE];
__device__ bf16 g_Kcos_hi[NE], g_Kcos_lo[NE];
__device__ bf16 g_Vp_hi[NE], g_Vp_lo[NE];

__device__ bf16 g_KVs_hi[KVN], g_KVs_lo[KVN];
__device__ bf16 g_KVc_hi[KVN], g_KVc_lo[KVN];

__device__ float g_Ks[B_DIM * E_DIM];
__device__ float g_Kc[B_DIM * E_DIM];
__device__ float g_KsP[16 * B_DIM * E_DIM];
__device__ float g_KcP[16 * B_DIM * E_DIM];
__device__ float g_Z[N_ROWS];

// ---------------------------------------------------------------------------
// Helpers
// ---------------------------------------------------------------------------
__device__ __forceinline__ unsigned smem_u32(const void* p) {
    return (unsigned)__cvta_generic_to_shared(p);
}
__device__ __forceinline__ void cp16(void* sdst, const void* gsrc) {
    asm volatile("cp.async.cg.shared.global [%0], [%1], 16;"
                 :: "r"(smem_u32(sdst)), "l"(gsrc));
}
#define CP_COMMIT() asm volatile("cp.async.commit_group;")
#define CP_WAIT0()  asm volatile("cp.async.wait_group 0;")

__device__ __forceinline__ void ldsm4(unsigned a, unsigned& r0, unsigned& r1,
                                      unsigned& r2, unsigned& r3) {
    asm volatile("ldmatrix.sync.aligned.m8n8.x4.shared.b16 {%0,%1,%2,%3},[%4];"
                 : "=r"(r0), "=r"(r1), "=r"(r2), "=r"(r3) : "r"(a));
}
__device__ __forceinline__ void ldsm4t(unsigned a, unsigned& r0, unsigned& r1,
                                       unsigned& r2, unsigned& r3) {
    asm volatile("ldmatrix.sync.aligned.m8n8.x4.trans.shared.b16 {%0,%1,%2,%3},[%4];"
                 : "=r"(r0), "=r"(r1), "=r"(r2), "=r"(r3) : "r"(a));
}
__device__ __forceinline__ void mma16816(float* c, const unsigned* a, const unsigned* b) {
    asm volatile(
        "mma.sync.aligned.m16n8k16.row.col.f32.bf16.bf16.f32 "
        "{%0,%1,%2,%3},{%4,%5,%6,%7},{%8,%9},{%0,%1,%2,%3};"
        : "+f"(c[0]), "+f"(c[1]), "+f"(c[2]), "+f"(c[3])
        : "r"(a[0]), "r"(a[1]), "r"(a[2]), "r"(a[3]), "r"(b[0]), "r"(b[1]));
}
__device__ __forceinline__ void split1(float v, bf16& h, bf16& l) {
    h = __float2bfloat16(v);
    l = __float2bfloat16(v - __bfloat162float(h));
}
__device__ __forceinline__ void store_split2(bf16* hi, bf16* lo, size_t idx,
                                             float v0, float v1) {
    bf16 h0, l0, h1, l1;
    split1(v0, h0, l0);
    split1(v1, h1, l1);
    bf162 th; th.x = h0; th.y = h1;
    bf162 tl; tl.x = l0; tl.y = l1;
    *reinterpret_cast<bf162*>(hi + idx) = th;
    *reinterpret_cast<bf162*>(lo + idx) = tl;
}

// ---------------------------------------------------------------------------
// Split fp32 -> bf16 hi/lo
// ---------------------------------------------------------------------------
__global__ __launch_bounds__(256)
void split_kernel(const float* __restrict__ x, bf16* __restrict__ hi,
                  bf16* __restrict__ lo, int n4) {
    int i = blockIdx.x * 256 + threadIdx.x;
    if (i >= n4) return;
    float4 v = reinterpret_cast<const float4*>(x)[i];
    bf16 h0, l0, h1, l1, h2, l2, h3, l3;
    split1(v.x, h0, l0); split1(v.y, h1, l1);
    split1(v.z, h2, l2); split1(v.w, h3, l3);
    bf162 a, b, c, d;
    a.x = h0; a.y = h1; b.x = h2; b.y = h3;
    c.x = l0; c.y = l1; d.x = l2; d.y = l3;
    reinterpret_cast<bf162*>(hi)[2 * i] = a;
    reinterpret_cast<bf162*>(hi)[2 * i + 1] = b;
    reinterpret_cast<bf162*>(lo)[2 * i] = c;
    reinterpret_cast<bf162*>(lo)[2 * i + 1] = d;
}

// ---------------------------------------------------------------------------
// Stage 1: projection GEMM (tensor, cp.async double-buffered).
// ---------------------------------------------------------------------------
template <int MODE>
__global__ __launch_bounds__(256)
void proj_mma(const bf16* __restrict__ Ah_g, const bf16* __restrict__ Al_g,
              const bf16* __restrict__ Bh_g, const bf16* __restrict__ Bl_g,
              const float* __restrict__ bias,
              bf16* __restrict__ O1h, bf16* __restrict__ O1l,
              bf16* __restrict__ O2h, bf16* __restrict__ O2l) {
    __shared__ bf16 Ah[2][128][24], Al[2][128][24];
    __shared__ bf16 Bh[2][64][24], Bl[2][64][24];

    const int tid = threadIdx.x, lane = tid & 31, w = tid >> 5;
    const int wm = (w & 3) * 32, wn = (w >> 2) * 32;
    const int m0 = blockIdx.y * 128, n0 = blockIdx.x * 64;

    const int ar = tid >> 1, ac = (tid & 1) * 8;   // A: 256 chunks of 16B
    const int br = tid >> 1, bc = (tid & 1) * 8;   // B: 128 chunks (tid<128)

    float c[2][4][4];
#pragma unroll
    for (int i = 0; i < 2; i++)
#pragma unroll
        for (int j = 0; j < 4; j++)
#pragma unroll
            for (int q = 0; q < 4; q++) c[i][j][q] = 0.f;

#define PROJ_LOAD(st, kt)                                                        \
    do {                                                                          \
        cp16(&Ah[st][ar][ac], &Ah_g[(size_t)(m0 + ar) * E_DIM + (kt) + ac]);      \
        cp16(&Al[st][ar][ac], &Al_g[(size_t)(m0 + ar) * E_DIM + (kt) + ac]);      \
        if (tid < 128) {                                                          \
            cp16(&Bh[st][br][bc], &Bh_g[(size_t)(n0 + br) * E_DIM + (kt) + bc]);  \
            cp16(&Bl[st][br][bc], &Bl_g[(size_t)(n0 + br) * E_DIM + (kt) + bc]);  \
        }                                                                         \
    } while (0)

    PROJ_LOAD(0, 0);
    CP_COMMIT();

    const int NITER = E_DIM / 16;
    for (int it = 0; it < NITER; it++) {
        CP_WAIT0();
        __syncthreads();
        if (it + 1 < NITER) {
            PROJ_LOAD((it + 1) & 1, (it + 1) * 16);
            CP_COMMIT();
        }
        const int st = it & 1;

        unsigned ah[2][4], al[2][4], bh[4][2], bl[4][2];
#pragma unroll
        for (int fi = 0; fi < 2; fi++) {
            ldsm4(smem_u32(&Ah[st][wm + fi * 16 + (lane & 15)][(lane >> 4) * 8]),
                  ah[fi][0], ah[fi][1], ah[fi][2], ah[fi][3]);
            ldsm4(smem_u32(&Al[st][wm + fi * 16 + (lane & 15)][(lane >> 4) * 8]),
                  al[fi][0], al[fi][1], al[fi][2], al[fi][3]);
        }
#pragma unroll
        for (int g = 0; g < 2; g++) {
            int nrow = wn + g * 16 + (lane >> 4) * 8 + (lane & 7);
            int kcol = ((lane >> 3) & 1) * 8;
            ldsm4(smem_u32(&Bh[st][nrow][kcol]),
                  bh[2 * g][0], bh[2 * g][1], bh[2 * g + 1][0], bh[2 * g + 1][1]);
            ldsm4(smem_u32(&Bl[st][nrow][kcol]),
                  bl[2 * g][0], bl[2 * g][1], bl[2 * g + 1][0], bl[2 * g + 1][1]);
        }
#pragma unroll
        for (int fi = 0; fi < 2; fi++)
#pragma unroll
            for (int fj = 0; fj < 4; fj++) {
                mma16816(c[fi][fj], ah[fi], bh[fj]);
                mma16816(c[fi][fj], ah[fi], bl[fj]);
                mma16816(c[fi][fj], al[fi], bh[fj]);
            }
    }
#undef PROJ_LOAD

    const int row = lane >> 2, col2 = (lane & 3) * 2;
#pragma unroll
    for (int fi = 0; fi < 2; fi++)
#pragma unroll
        for (int h = 0; h < 2; h++) {
            int m = m0 + wm + fi * 16 + row + h * 8;
            float sl = 0.f, cl = 0.f;
            if (MODE == 1) {
                float th = HALF_PI * (float)((m >> 2) + 1) * (1.0f / 2048.0f);
                sl = sinf(th); cl = cosf(th);
            }
#pragma unroll
            for (int fj = 0; fj < 4; fj++) {
                int n = n0 + wn + fj * 8 + col2;
                float v0 = c[fi][fj][h * 2 + 0] + bias[n];
                float v1 = c[fi][fj][h * 2 + 1] + bias[n + 1];
                if (MODE != 2) { v0 = fmaxf(v0, 0.f); v1 = fmaxf(v1, 0.f); }
                size_t idx = (size_t)m * E_DIM + n;
                if (MODE == 1) {
                    store_split2(O1h, O1l, idx, sl * v0, sl * v1);
                    store_split2(O2h, O2l, idx, cl * v0, cl * v1);
                } else {
                    store_split2(O1h, O1l, idx, v0, v1);
                }
            }
        }
}

// ---------------------------------------------------------------------------
// Stage 2: dual KV-state GEMM (per batch, cp.async double-buffered).
// ---------------------------------------------------------------------------
__global__ __launch_bounds__(256)
void kv_mma() {
    __shared__ bf16 Ash[2][16][136], Asl[2][16][136], Ach[2][16][136], Acl[2][16][136];
    __shared__ bf16 Bh[2][16][72], Bl[2][16][72];

    const int tid = threadIdx.x, lane = tid & 31, w = tid >> 5;
    const int wm = (w & 3) * 32, wn = (w >> 2) * 32;
    const int b = blockIdx.z;
    const int e0 = blockIdx.y * 128, n0 = blockIdx.x * 64;

    const int asr = tid >> 4, asc = (tid & 15) * 8;  // A: 256 chunks
    const int bsr = tid >> 3, bsc = (tid & 7) * 8;   // B: 128 chunks (tid<128)

    float cs[2][4][4], cc[2][4][4];
#pragma unroll
    for (int i = 0; i < 2; i++)
#pragma unroll
        for (int j = 0; j < 4; j++)
#pragma unroll
            for (int q = 0; q < 4; q++) { cs[i][j][q] = 0.f; cc[i][j][q] = 0.f; }

#define KV_LOAD(st, s0)                                                              \
    do {                                                                              \
        size_t ga = ((size_t)((s0) + asr) * B_DIM + b) * E_DIM + e0 + asc;            \
        cp16(&Ash[st][asr][asc], &g_Ksin_hi[ga]);                                     \
        cp16(&Asl[st][asr][asc], &g_Ksin_lo[ga]);                                     \
        cp16(&Ach[st][asr][asc], &g_Kcos_hi[ga]);                                     \
        cp16(&Acl[st][asr][asc], &g_Kcos_lo[ga]);                                     \
        if (tid < 128) {                                                              \
            size_t gb = ((size_t)((s0) + bsr) * B_DIM + b) * E_DIM + n0 + bsc;        \
            cp16(&Bh[st][bsr][bsc], &g_Vp_hi[gb]);                                    \
            cp16(&Bl[st][bsr][bsc], &g_Vp_lo[gb]);                                    \
        }                                                                             \
    } while (0)

    KV_LOAD(0, 0);
    CP_COMMIT();

    const int NITER = L_DIM / 16;
    for (int it = 0; it < NITER; it++) {
        CP_WAIT0();
        __syncthreads();
        if (it + 1 < NITER) {
            KV_LOAD((it + 1) & 1, (it + 1) * 16);
            CP_COMMIT();
        }
        const int st = it & 1;

        unsigned bhf[4][2], blf[4][2];
        {
            int krow = ((lane >> 3) & 1) * 8 + (lane & 7);
#pragma unroll
            for (int g = 0; g < 2; g++) {
                int ncol = wn + g * 16 + (lane >> 4) * 8;
                ldsm4t(smem_u32(&Bh[st][krow][ncol]),
                       bhf[2 * g][0], bhf[2 * g][1], bhf[2 * g + 1][0], bhf[2 * g + 1][1]);
                ldsm4t(smem_u32(&Bl[st][krow][ncol]),
                       blf[2 * g][0], blf[2 * g][1], blf[2 * g + 1][0], blf[2 * g + 1][1]);
            }
        }
#pragma unroll
        for (int fi = 0; fi < 2; fi++) {
            int krow = (lane & 7) + (lane >> 4) * 8;
            int mcol = wm + fi * 16 + ((lane >> 3) & 1) * 8;
            unsigned ash[4], asl_[4], ach[4], acl_[4];
            ldsm4t(smem_u32(&Ash[st][krow][mcol]), ash[0], ash[1], ash[2], ash[3]);
            ldsm4t(smem_u32(&Asl[st][krow][mcol]), asl_[0], asl_[1], asl_[2], asl_[3]);
            ldsm4t(smem_u32(&Ach[st][krow][mcol]), ach[0], ach[1], ach[2], ach[3]);
            ldsm4t(smem_u32(&Acl[st][krow][mcol]), acl_[0], acl_[1], acl_[2], acl_[3]);
#pragma unroll
            for (int fj = 0; fj < 4; fj++) {
                mma16816(cs[fi][fj], ash, bhf[fj]);
                mma16816(cs[fi][fj], ash, blf[fj]);
                mma16816(cs[fi][fj], asl_, bhf[fj]);
                mma16816(cc[fi][fj], ach, bhf[fj]);
                mma16816(cc[fi][fj], ach, blf[fj]);
                mma16816(cc[fi][fj], acl_, bhf[fj]);
            }
        }
    }
#undef KV_LOAD

    const int row = lane >> 2, col2 = (lane & 3) * 2;
#pragma unroll
    for (int fi = 0; fi < 2; fi++)
#pragma unroll
        for (int h = 0; h < 2; h++) {
            int e = e0 + wm + fi * 16 + row + h * 8;
#pragma unroll
            for (int fj = 0; fj < 4; fj++) {
                int m = n0 + wn + fj * 8 + col2;
                size_t idx = ((size_t)b * E_DIM + e) * E_DIM + m;
                store_split2(g_KVs_hi, g_KVs_lo, idx, cs[fi][fj][h * 2], cs[fi][fj][h * 2 + 1]);
                store_split2(g_KVc_hi, g_KVc_lo, idx, cc[fi][fj][h * 2], cc[fi][fj][h * 2 + 1]);
            }
        }
}

// ---------------------------------------------------------------------------
// Column sums of sin/cos-scaled K.
// ---------------------------------------------------------------------------
__global__ __launch_bounds__(256)
void colsum_kernel() {
    const int idx = blockIdx.x * 256 + threadIdx.x;
    const int s0 = blockIdx.y * 128;
    float as = 0.f, ac = 0.f;
#pragma unroll 4
    for (int j = 0; j < 128; j++) {
        size_t g = (size_t)(s0 + j) * (B_DIM * E_DIM) + idx;
        as += __bfloat162float(g_Ksin_hi[g]) + __bfloat162float(g_Ksin_lo[g]);
        ac += __bfloat162float(g_Kcos_hi[g]) + __bfloat162float(g_Kcos_lo[g]);
    }
    g_KsP[blockIdx.y * (B_DIM * E_DIM) + idx] = as;
    g_KcP[blockIdx.y * (B_DIM * E_DIM) + idx] = ac;
}

__global__ __launch_bounds__(256)
void colsum_reduce_kernel() {
    const int idx = blockIdx.x * 256 + threadIdx.x;
    float as = 0.f, ac = 0.f;
#pragma unroll
    for (int t = 0; t < 16; t++) {
        as += g_KsP[t * (B_DIM * E_DIM) + idx];
        ac += g_KcP[t * (B_DIM * E_DIM) + idx];
    }
    g_Ks[idx] = as;
    g_Kc[idx] = ac;
}

// ---------------------------------------------------------------------------
// Normalizer
// ---------------------------------------------------------------------------
__global__ __launch_bounds__(256)
void z_kernel() {
    const int warp = threadIdx.x >> 5, lane = threadIdx.x & 31;
    const int n = blockIdx.x * 8 + warp;
    const int b = n & 3, l = n >> 2;
    float ds = 0.f, dc = 0.f;
    for (int e = lane * 8; e < E_DIM; e += 256) {
        uint4 qh = *reinterpret_cast<const uint4*>(&g_Qp_hi[(size_t)n * E_DIM + e]);
        uint4 ql = *reinterpret_cast<const uint4*>(&g_Qp_lo[(size_t)n * E_DIM + e]);
        const bf162* ph = reinterpret_cast<const bf162*>(&qh);
        const bf162* pl = reinterpret_cast<const bf162*>(&ql);
        float q[8];
#pragma unroll
        for (int i = 0; i < 4; i++) {
            q[2 * i]     = __bfloat162float(ph[i].x) + __bfloat162float(pl[i].x);
            q[2 * i + 1] = __bfloat162float(ph[i].y) + __bfloat162float(pl[i].y);
        }
        float4 k0 = *reinterpret_cast<const float4*>(&g_Ks[b * E_DIM + e]);
        float4 k1 = *reinterpret_cast<const float4*>(&g_Ks[b * E_DIM + e + 4]);
        float4 c0 = *reinterpret_cast<const float4*>(&g_Kc[b * E_DIM + e]);
        float4 c1 = *reinterpret_cast<const float4*>(&g_Kc[b * E_DIM + e + 4]);
        ds += q[0]*k0.x + q[1]*k0.y + q[2]*k0.z + q[3]*k0.w
            + q[4]*k1.x + q[5]*k1.y + q[6]*k1.z + q[7]*k1.w;
        dc += q[0]*c0.x + q[1]*c0.y + q[2]*c0.z + q[3]*c0.w
            + q[4]*c1.x + q[5]*c1.y + q[6]*c1.z + q[7]*c1.w;
    }
#pragma unroll
    for (int o = 16; o; o >>= 1) {
        ds += __shfl_down_sync(0xFFFFFFFFu, ds, o);
        dc += __shfl_down_sync(0xFFFFFFFFu, dc, o);
    }
    if (lane == 0) {
        float th = HALF_PI * (float)(l + 1) * (1.0f / 2048.0f);
        float d = sinf(th) * ds + cosf(th) * dc;
        g_Z[n] = 1.0f / fmaxf(d, EPS_F);
    }
}

// ---------------------------------------------------------------------------
// Stage 3: output dual GEMM (per batch, cp.async double-buffered).
// ---------------------------------------------------------------------------
__global__ __launch_bounds__(256)
void out_mma(float* __restrict__ O) {
    __shared__ bf16 Ah[2][128][24], Al[2][128][24];
    __shared__ bf16 Bsh[2][16][72], Bsl[2][16][72], Bch[2][16][72], Bcl[2][16][72];

    const int tid = threadIdx.x, lane = tid & 31, w = tid >> 5;
    const int wm = (w & 3) * 32, wn = (w >> 2) * 32;
    const int b = blockIdx.z;
    const int l0 = blockIdx.y * 128, n0 = blockIdx.x * 64;

    const int ar = tid >> 1, ac = (tid & 1) * 8;
    const int bsr = tid >> 3, bsc = (tid & 7) * 8;

    float cs[2][4][4], cc[2][4][4];
#pragma unroll
    for (int i = 0; i < 2; i++)
#pragma unroll
        for (int j = 0; j < 4; j++)
#pragma unroll
            for (int q = 0; q < 4; q++) { cs[i][j][q] = 0.f; cc[i][j][q] = 0.f; }

#define OUT_LOAD(st, kt)                                                           \
    do {                                                                            \
        size_t ga = ((size_t)(l0 + ar) * B_DIM + b) * E_DIM + (kt) + ac;            \
        cp16(&Ah[st][ar][ac], &g_Qp_hi[ga]);                                        \
        cp16(&Al[st][ar][ac], &g_Qp_lo[ga]);                                        \
        if (tid < 128) {                                                            \
            size_t gb = ((size_t)b * E_DIM + (kt) + bsr) * E_DIM + n0 + bsc;        \
            cp16(&Bsh[st][bsr][bsc], &g_KVs_hi[gb]);                                \
            cp16(&Bsl[st][bsr][bsc], &g_KVs_lo[gb]);                                \
            cp16(&Bch[st][bsr][bsc], &g_KVc_hi[gb]);                                \
            cp16(&Bcl[st][bsr][bsc], &g_KVc_lo[gb]);                                \
        }                                                                           \
    } while (0)

    OUT_LOAD(0, 0);
    CP_COMMIT();

    const int NITER = E_DIM / 16;
    for (int it = 0; it < NITER; it++) {
        CP_WAIT0();
        __syncthreads();
        if (it + 1 < NITER) {
            OUT_LOAD((it + 1) & 1, (it + 1) * 16);
            CP_COMMIT();
        }
        const int st = it & 1;

        unsigned bsh[4][2], bsl_[4][2], bch[4][2], bcl_[4][2];
        {
            int krow = ((lane >> 3) & 1) * 8 + (lane & 7);
#pragma unroll
            for (int g = 0; g < 2; g++) {
                int ncol = wn + g * 16 + (lane >> 4) * 8;
                ldsm4t(smem_u32(&Bsh[st][krow][ncol]),
                       bsh[2*g][0], bsh[2*g][1], bsh[2*g+1][0], bsh[2*g+1][1]);
                ldsm4t(smem_u32(&Bsl[st][krow][ncol]),
                       bsl_[2*g][0], bsl_[2*g][1], bsl_[2*g+1][0], bsl_[2*g+1][1]);
                ldsm4t(smem_u32(&Bch[st][krow][ncol]),
                       bch[2*g][0], bch[2*g][1], bch[2*g+1][0], bch[2*g+1][1]);
                ldsm4t(smem_u32(&Bcl[st][krow][ncol]),
                       bcl_[2*g][0], bcl_[2*g][1], bcl_[2*g+1][0], bcl_[2*g+1][1]);
            }
        }
#pragma unroll
        for (int fi = 0; fi < 2; fi++) {
            unsigned ah[4], al_[4];
            ldsm4(smem_u32(&Ah[st][wm + fi * 16 + (lane & 15)][(lane >> 4) * 8]),
                  ah[0], ah[1], ah[2], ah[3]);
            ldsm4(smem_u32(&Al[st][wm + fi * 16 + (lane & 15)][(lane >> 4) * 8]),
                  al_[0], al_[1], al_[2], al_[3]);
#pragma unroll
            for (int fj = 0; fj < 4; fj++) {
                mma16816(cs[fi][fj], ah, bsh[fj]);
                mma16816(cs[fi][fj], ah, bsl_[fj]);
                mma16816(cs[fi][fj], al_, bsh[fj]);
                mma16816(cc[fi][fj], ah, bch[fj]);
                mma16816(cc[fi][fj], ah, bcl_[fj]);
                mma16816(cc[fi][fj], al_, bch[fj]);
            }
        }
    }
#undef OUT_LOAD

    const int row = lane >> 2, col2 = (lane & 3) * 2;
#pragma unroll
    for (int fi = 0; fi < 2; fi++)
#pragma unroll
        for (int h = 0; h < 2; h++) {
            int l = l0 + wm + fi * 16 + row + h * 8;
            float th = HALF_PI * (float)(l + 1) * (1.0f / 2048.0f);
            float sl = sinf(th), cl = cosf(th);
            float zz = g_Z[l * B_DIM + b];
#pragma unroll
            for (int fj = 0; fj < 4; fj++) {
                int n = n0 + wn + fj * 8 + col2;
                float2 o;
                o.x = zz * (sl * cs[fi][fj][h * 2]     + cl * cc[fi][fj][h * 2]);
                o.y = zz * (sl * cs[fi][fj][h * 2 + 1] + cl * cc[fi][fj][h * 2 + 1]);
                *reinterpret_cast<float2*>(&O[((size_t)l * B_DIM + b) * E_DIM + n]) = o;
            }
        }
}

// ---------------------------------------------------------------------------
// Launch
// ---------------------------------------------------------------------------
extern "C" void kernel_launch(void* const* d_in, const int* in_sizes, int n_in,
                              void* d_out, int out_size) {
    const float* query = (const float*)d_in[0];
    const float* key   = (const float*)d_in[1];
    const float* value = (const float*)d_in[2];
    const float* Wq    = (const float*)d_in[3];
    const float* bq    = (const float*)d_in[4];
    const float* Wk    = (const float*)d_in[5];
    const float* bk    = (const float*)d_in[6];
    const float* Wv    = (const float*)d_in[7];
    const float* bv    = (const float*)d_in[8];
    float* out = (float*)d_out;

    bf16 *sq_hi, *sq_lo, *sk_hi, *sk_lo, *sv_hi, *sv_lo;
    bf16 *wq_hi, *wq_lo, *wk_hi, *wk_lo, *wv_hi, *wv_lo;
    bf16 *Qp_hi, *Qp_lo, *Ksin_hi, *Ksin_lo, *Kcos_hi, *Kcos_lo, *Vp_hi, *Vp_lo;
    cudaGetSymbolAddress((void**)&sq_hi, g_sq_hi);
    cudaGetSymbolAddress((void**)&sq_lo, g_sq_lo);
    cudaGetSymbolAddress((void**)&sk_hi, g_sk_hi);
    cudaGetSymbolAddress((void**)&sk_lo, g_sk_lo);
    cudaGetSymbolAddress((void**)&sv_hi, g_sv_hi);
    cudaGetSymbolAddress((void**)&sv_lo, g_sv_lo);
    cudaGetSymbolAddress((void**)&wq_hi, g_wq_hi);
    cudaGetSymbolAddress((void**)&wq_lo, g_wq_lo);
    cudaGetSymbolAddress((void**)&wk_hi, g_wk_hi);
    cudaGetSymbolAddress((void**)&wk_lo, g_wk_lo);
    cudaGetSymbolAddress((void**)&wv_hi, g_wv_hi);
    cudaGetSymbolAddress((void**)&wv_lo, g_wv_lo);
    cudaGetSymbolAddress((void**)&Qp_hi, g_Qp_hi);
    cudaGetSymbolAddress((void**)&Qp_lo, g_Qp_lo);
    cudaGetSymbolAddress((void**)&Ksin_hi, g_Ksin_hi);
    cudaGetSymbolAddress((void**)&Ksin_lo, g_Ksin_lo);
    cudaGetSymbolAddress((void**)&Kcos_hi, g_Kcos_hi);
    cudaGetSymbolAddress((void**)&Kcos_lo, g_Kcos_lo);
    cudaGetSymbolAddress((void**)&Vp_hi, g_Vp_hi);
    cudaGetSymbolAddress((void**)&Vp_lo, g_Vp_lo);

    split_kernel<<<NE / 4 / 256, 256>>>(query, sq_hi, sq_lo, NE / 4);
    split_kernel<<<NE / 4 / 256, 256>>>(key,   sk_hi, sk_lo, NE / 4);
    split_kernel<<<NE / 4 / 256, 256>>>(value, sv_hi, sv_lo, NE / 4);
    split_kernel<<<WE / 4 / 256, 256>>>(Wq, wq_hi, wq_lo, WE / 4);
    split_kernel<<<WE / 4 / 256, 256>>>(Wk, wk_hi, wk_lo, WE / 4);
    split_kernel<<<WE / 4 / 256, 256>>>(Wv, wv_hi, wv_lo, WE / 4);

    dim3 projGrid(E_DIM / 64, N_ROWS / 128);   // (16, 64)
    proj_mma<0><<<projGrid, 256>>>(sq_hi, sq_lo, wq_hi, wq_lo, bq,
                                   Qp_hi, Qp_lo, nullptr, nullptr);
    proj_mma<1><<<projGrid, 256>>>(sk_hi, sk_lo, wk_hi, wk_lo, bk,
                                   Ksin_hi, Ksin_lo, Kcos_hi, Kcos_lo);
    proj_mma<2><<<projGrid, 256>>>(sv_hi, sv_lo, wv_hi, wv_lo, bv,
                                   Vp_hi, Vp_lo, nullptr, nullptr);

    dim3 csGrid(16, 16);
    colsum_kernel<<<csGrid, 256>>>();
    colsum_reduce_kernel<<<16, 256>>>();
    z_kernel<<<N_ROWS / 8, 256>>>();

    dim3 kvGrid(E_DIM / 64, E_DIM / 128, B_DIM);   // (16, 8, 4)
    kv_mma<<<kvGrid, 256>>>();

    dim3 outGrid(E_DIM / 64, L_DIM / 128, B_DIM);  // (16, 16, 4)
    out_mma<<<outGrid, 256>>>(out);
}